// round 1
// baseline (speedup 1.0000x reference)
#include <cuda_runtime.h>
#include <math.h>

#define TWO_B 32768
#define B_HALF 16384
#define DIM 256
#define KC 1024

// ---------------- device scratch (static, no allocation) ----------------
__device__ float g_zn[(size_t)TWO_B * DIM];   // normalized z
__device__ float g_pn[(size_t)TWO_B * DIM];   // normalized p
__device__ float g_cn[(size_t)KC * DIM];      // normalized centers
__device__ float g_nz[TWO_B];                 // squared norms of normalized rows (~1)
__device__ float g_np[TWO_B];
__device__ float g_nc[KC];
__device__ float g_tz[(size_t)TWO_B * KC];    // t = D/eps for z  (128 MB)
__device__ float g_tp[(size_t)TWO_B * KC];    // t = D/eps for p  (128 MB)
__device__ float g_cs[4 * KC];                // column sums of exp(t): z1,z2,p1,p2
__device__ float g_lcs[4 * KC];               // log of column sums
__device__ double g_loss;

// ---------------- kernels ----------------
__global__ void zero_kernel() {
    int i = blockIdx.x * blockDim.x + threadIdx.x;
    if (i < 4 * KC) g_cs[i] = 0.0f;
    if (i == 0) g_loss = 0.0;
}

__global__ void normalize_kernel(const float* __restrict__ z,
                                 const float* __restrict__ p,
                                 const float* __restrict__ c) {
    __shared__ float red[256];
    int row = blockIdx.x;
    const float* src; float* dst; float* nsq; int r;
    if (row < TWO_B)          { src = z; dst = g_zn; nsq = g_nz; r = row; }
    else if (row < 2 * TWO_B) { src = p; dst = g_pn; nsq = g_np; r = row - TWO_B; }
    else                      { src = c; dst = g_cn; nsq = g_nc; r = row - 2 * TWO_B; }
    int t = threadIdx.x;
    float x = src[(size_t)r * DIM + t];
    red[t] = x * x;
    __syncthreads();
    for (int s = 128; s > 0; s >>= 1) {
        if (t < s) red[t] += red[t + s];
        __syncthreads();
    }
    float ss = red[0];
    float inv = 1.0f / fmaxf(sqrtf(ss), 1e-12f);
    dst[(size_t)r * DIM + t] = x * inv;
    if (t == 0) nsq[r] = ss * inv * inv;
}

#define BM 128
#define BN 128
#define BK 16

// G = A @ C^T, epilogue: t = 20*sqrt(max(na+nc-2g,1e-12)), store t,
// and accumulate column sums of exp(t) into g_cs (shared reduction + atomics).
__global__ __launch_bounds__(256, 2) void gemm_dist_kernel(int which) {
    const float* __restrict__ A  = which ? g_pn : g_zn;
    const float* __restrict__ na = which ? g_np : g_nz;
    float* __restrict__ T        = which ? g_tp : g_tz;

    __shared__ float As[BK][BM + 4];
    __shared__ float Bs[BK][BN + 4];
    __shared__ float colacc[BN];

    int bm = blockIdx.y;
    int bn = blockIdx.x;
    int tid = threadIdx.x;
    int tm = tid >> 4;
    int tn = tid & 15;

    float acc[8][8];
    #pragma unroll
    for (int i = 0; i < 8; i++)
        #pragma unroll
        for (int j = 0; j < 8; j++)
            acc[i][j] = 0.0f;

    const float* Ab = A + (size_t)bm * BM * DIM;
    const float* Cb = g_cn + (size_t)bn * BN * DIM;

    for (int k0 = 0; k0 < DIM; k0 += BK) {
        #pragma unroll
        for (int l = 0; l < 2; l++) {
            int idx = (tid + l * 256) * 4;
            int row = idx >> 4;
            int col = idx & 15;
            float4 va = *reinterpret_cast<const float4*>(Ab + (size_t)row * DIM + k0 + col);
            As[col + 0][row] = va.x;
            As[col + 1][row] = va.y;
            As[col + 2][row] = va.z;
            As[col + 3][row] = va.w;
            float4 vb = *reinterpret_cast<const float4*>(Cb + (size_t)row * DIM + k0 + col);
            Bs[col + 0][row] = vb.x;
            Bs[col + 1][row] = vb.y;
            Bs[col + 2][row] = vb.z;
            Bs[col + 3][row] = vb.w;
        }
        __syncthreads();
        #pragma unroll
        for (int kk = 0; kk < BK; kk++) {
            float4 a0 = *reinterpret_cast<const float4*>(&As[kk][tm * 8]);
            float4 a1 = *reinterpret_cast<const float4*>(&As[kk][tm * 8 + 4]);
            float4 b0 = *reinterpret_cast<const float4*>(&Bs[kk][tn * 8]);
            float4 b1 = *reinterpret_cast<const float4*>(&Bs[kk][tn * 8 + 4]);
            float ra[8] = {a0.x, a0.y, a0.z, a0.w, a1.x, a1.y, a1.z, a1.w};
            float rb[8] = {b0.x, b0.y, b0.z, b0.w, b1.x, b1.y, b1.z, b1.w};
            #pragma unroll
            for (int i = 0; i < 8; i++)
                #pragma unroll
                for (int j = 0; j < 8; j++)
                    acc[i][j] = fmaf(ra[i], rb[j], acc[i][j]);
        }
        __syncthreads();
    }

    if (tid < BN) colacc[tid] = 0.0f;
    __syncthreads();

    float nam[8], ncn[8];
    #pragma unroll
    for (int i = 0; i < 8; i++) nam[i] = na[bm * BM + tm * 8 + i];
    #pragma unroll
    for (int j = 0; j < 8; j++) ncn[j] = g_nc[bn * BN + tn * 8 + j];

    float es[8];
    #pragma unroll
    for (int j = 0; j < 8; j++) es[j] = 0.0f;

    #pragma unroll
    for (int i = 0; i < 8; i++) {
        float tv[8];
        #pragma unroll
        for (int j = 0; j < 8; j++) {
            float sq = nam[i] + ncn[j] - 2.0f * acc[i][j];
            float d = sqrtf(fmaxf(sq, 1e-12f));
            float tt = d * 20.0f;   // 1/epsilon
            tv[j] = tt;
            es[j] += expf(tt);
        }
        size_t base = (size_t)(bm * BM + tm * 8 + i) * KC + bn * BN + tn * 8;
        *reinterpret_cast<float4*>(T + base)     = make_float4(tv[0], tv[1], tv[2], tv[3]);
        *reinterpret_cast<float4*>(T + base + 4) = make_float4(tv[4], tv[5], tv[6], tv[7]);
    }

    #pragma unroll
    for (int j = 0; j < 8; j++)
        atomicAdd(&colacc[tn * 8 + j], es[j]);
    __syncthreads();

    int half = bm >> 7;  // rows [0,16384) -> half 0, else half 1
    int csbase = (which * 2 + half) * KC;
    if (tid < BN)
        atomicAdd(&g_cs[csbase + bn * BN + tid], colacc[tid]);
}

__global__ void logcs_kernel() {
    int i = blockIdx.x * blockDim.x + threadIdx.x;
    if (i < 4 * KC) g_lcs[i] = logf(g_cs[i]);
}

__device__ __forceinline__ float block_reduce(float v, float* red) {
    int t = threadIdx.x;
    red[t] = v;
    __syncthreads();
    for (int s = 128; s > 0; s >>= 1) {
        if (t < s) red[t] += red[t + s];
        __syncthreads();
    }
    float r = red[0];
    __syncthreads();
    return r;
}

// one block per batch row b: compute all four row-softmax normalizers and the
// cross-entropy contraction in a single pass over the 4 x 1024 row slice.
__global__ __launch_bounds__(256) void final_kernel() {
    __shared__ float red[256];
    int b = blockIdx.x;
    int t = threadIdx.x;

    float az1[4], az2[4], lp[4];
    float az1s = 0.f, az2s = 0.f, ap1s = 0.f, ap2s = 0.f;
    #pragma unroll
    for (int j = 0; j < 4; j++) {
        int k = t + j * 256;
        float tz1 = g_tz[(size_t)b * KC + k];
        float tz2 = g_tz[(size_t)(b + B_HALF) * KC + k];
        float tp1 = g_tp[(size_t)b * KC + k];
        float tp2 = g_tp[(size_t)(b + B_HALF) * KC + k];
        float u1 = tz1 - g_lcs[k];
        float u2 = tz2 - g_lcs[KC + k];
        float v1 = tp1 - g_lcs[2 * KC + k];
        float v2 = tp2 - g_lcs[3 * KC + k];
        az1[j] = expf(u1); az1s += az1[j];
        az2[j] = expf(u2); az2s += az2[j];
        ap1s += expf(v1);
        ap2s += expf(v2);
        lp[j] = v1 + v2;     // log pa1 + log pa2, minus row-log terms added later
    }
    float rz1 = block_reduce(az1s, red);
    float rz2 = block_reduce(az2s, red);
    float rp1 = block_reduce(ap1s, red);
    float rp2 = block_reduce(ap2s, red);
    float lr = logf(rp1) + logf(rp2);
    float irz1 = 1.0f / rz1;
    float irz2 = 1.0f / rz2;
    float dot = 0.f;
    #pragma unroll
    for (int j = 0; j < 4; j++)
        dot += (az1[j] * irz1 + az2[j] * irz2) * (lp[j] - lr);
    float dt = block_reduce(dot, red);
    if (t == 0)
        atomicAdd(&g_loss, -(double)dt / (4.0 * (double)B_HALF));
}

__global__ void finalize_kernel(float* out) {
    out[0] = (float)g_loss;
}

// ---------------- launch ----------------
extern "C" void kernel_launch(void* const* d_in, const int* in_sizes, int n_in,
                              void* d_out, int out_size) {
    const float* z = (const float*)d_in[0];
    const float* p = (const float*)d_in[1];
    const float* c = (const float*)d_in[2];
    float* out = (float*)d_out;

    zero_kernel<<<16, 256>>>();
    normalize_kernel<<<2 * TWO_B + KC, 256>>>(z, p, c);
    dim3 ggrid(KC / BN, TWO_B / BM);
    gemm_dist_kernel<<<ggrid, 256>>>(0);
    gemm_dist_kernel<<<ggrid, 256>>>(1);
    logcs_kernel<<<16, 256>>>();
    final_kernel<<<B_HALF, 256>>>();
    finalize_kernel<<<1, 1>>>(out);
}

// round 2
// speedup vs baseline: 1.2186x; 1.2186x over previous
#include <cuda_runtime.h>
#include <math.h>

#define TWO_B 32768
#define B_HALF 16384
#define DIM 256
#define KC 1024
#define BM 128
#define BN 128
#define BK 16

// ---------------- device scratch (static, no allocation) ----------------
__device__ float g_zn[(size_t)TWO_B * DIM];
__device__ float g_pn[(size_t)TWO_B * DIM];
__device__ float g_cn[(size_t)KC * DIM];
__device__ float g_nz[TWO_B];
__device__ float g_np[TWO_B];
__device__ float g_nc[KC];
__device__ float g_tz[(size_t)TWO_B * KC];
__device__ float g_tp[(size_t)TWO_B * KC];
__device__ float g_cs[4 * KC];
__device__ float g_lcs[4 * KC];
__device__ double g_loss;

// ---------------- helpers ----------------
__device__ __forceinline__ float tf32r(float x) {
    unsigned u;
    asm("cvt.rna.tf32.f32 %0, %1;" : "=r"(u) : "f"(x));
    return __uint_as_float(u);
}

__device__ __forceinline__ void mma_tf32(float* c, const unsigned* a, const unsigned* b) {
    asm volatile(
        "mma.sync.aligned.m16n8k8.row.col.f32.tf32.tf32.f32 "
        "{%0,%1,%2,%3}, {%4,%5,%6,%7}, {%8,%9}, {%0,%1,%2,%3};"
        : "+f"(c[0]), "+f"(c[1]), "+f"(c[2]), "+f"(c[3])
        : "r"(a[0]), "r"(a[1]), "r"(a[2]), "r"(a[3]), "r"(b[0]), "r"(b[1]));
}

__device__ __forceinline__ float distf(float sq) {
    return 20.0f * sqrtf(fmaxf(sq, 1e-12f));
}

// ---------------- kernels ----------------
__global__ void zero_kernel() {
    int i = blockIdx.x * blockDim.x + threadIdx.x;
    if (i < 4 * KC) g_cs[i] = 0.0f;
    if (i == 0) g_loss = 0.0;
}

__global__ void normalize_kernel(const float* __restrict__ z,
                                 const float* __restrict__ p,
                                 const float* __restrict__ c) {
    __shared__ float red[256];
    int row = blockIdx.x;
    const float* src; float* dst; float* nsq; int r;
    if (row < TWO_B)          { src = z; dst = g_zn; nsq = g_nz; r = row; }
    else if (row < 2 * TWO_B) { src = p; dst = g_pn; nsq = g_np; r = row - TWO_B; }
    else                      { src = c; dst = g_cn; nsq = g_nc; r = row - 2 * TWO_B; }
    int t = threadIdx.x;
    float x = src[(size_t)r * DIM + t];
    red[t] = x * x;
    __syncthreads();
    for (int s = 128; s > 0; s >>= 1) {
        if (t < s) red[t] += red[t + s];
        __syncthreads();
    }
    float ss = red[0];
    float inv = 1.0f / fmaxf(sqrtf(ss), 1e-12f);
    dst[(size_t)r * DIM + t] = x * inv;
    if (t == 0) nsq[r] = ss * inv * inv;
}

// Tensor-core tf32 GEMM + fused distance/exp epilogue.
// grid = (KC/BN, TWO_B/BM, 2), block = 256
__global__ __launch_bounds__(256) void gemm_dist_tc() {
    int which = blockIdx.z;
    const float* __restrict__ A  = which ? g_pn : g_zn;
    const float* __restrict__ na = which ? g_np : g_nz;
    float* __restrict__ T        = which ? g_tp : g_tz;

    __shared__ float As[2][BM][20];   // 16 used + 4 pad (conflict-free reads, aligned STS.128)
    __shared__ float Bs[2][BN][20];
    __shared__ float colacc[BN];

    int tid = threadIdx.x;
    int lane = tid & 31;
    int wid = tid >> 5;
    int wm = wid >> 2;    // 0..1
    int wn = wid & 3;     // 0..3
    int q = lane & 3;
    int gr = lane >> 2;

    int bm = blockIdx.y;
    int bn = blockIdx.x;

    const float* Ab = A + (size_t)(bm * BM) * DIM;
    const float* Cb = g_cn + (size_t)(bn * BN) * DIM;

    int lrow = tid >> 1;        // 0..127
    int lk   = (tid & 1) * 8;   // 0 or 8

    float acc[4][4][4];
    #pragma unroll
    for (int i = 0; i < 4; i++)
        #pragma unroll
        for (int j = 0; j < 4; j++)
            #pragma unroll
            for (int k = 0; k < 4; k++)
                acc[i][j][k] = 0.0f;

    const float* Arow = Ab + (size_t)lrow * DIM + lk;
    const float* Brow = Cb + (size_t)lrow * DIM + lk;

    float4 pa0 = *(const float4*)(Arow);
    float4 pa1 = *(const float4*)(Arow + 4);
    float4 pb0 = *(const float4*)(Brow);
    float4 pb1 = *(const float4*)(Brow + 4);

    #pragma unroll 4
    for (int s = 0; s < DIM / BK; s++) {
        int buf = s & 1;
        *(float4*)&As[buf][lrow][lk + 0] =
            make_float4(tf32r(pa0.x), tf32r(pa0.y), tf32r(pa0.z), tf32r(pa0.w));
        *(float4*)&As[buf][lrow][lk + 4] =
            make_float4(tf32r(pa1.x), tf32r(pa1.y), tf32r(pa1.z), tf32r(pa1.w));
        *(float4*)&Bs[buf][lrow][lk + 0] =
            make_float4(tf32r(pb0.x), tf32r(pb0.y), tf32r(pb0.z), tf32r(pb0.w));
        *(float4*)&Bs[buf][lrow][lk + 4] =
            make_float4(tf32r(pb1.x), tf32r(pb1.y), tf32r(pb1.z), tf32r(pb1.w));
        __syncthreads();

        if (s + 1 < DIM / BK) {
            int off = (s + 1) * BK;
            pa0 = *(const float4*)(Arow + off);
            pa1 = *(const float4*)(Arow + off + 4);
            pb0 = *(const float4*)(Brow + off);
            pb1 = *(const float4*)(Brow + off + 4);
        }

        #pragma unroll
        for (int k8 = 0; k8 < 2; k8++) {
            unsigned af[4][4], bf[4][2];
            #pragma unroll
            for (int mt = 0; mt < 4; mt++) {
                int r = wm * 64 + mt * 16 + gr;
                af[mt][0] = __float_as_uint(As[buf][r][k8 * 8 + q]);
                af[mt][1] = __float_as_uint(As[buf][r + 8][k8 * 8 + q]);
                af[mt][2] = __float_as_uint(As[buf][r][k8 * 8 + q + 4]);
                af[mt][3] = __float_as_uint(As[buf][r + 8][k8 * 8 + q + 4]);
            }
            #pragma unroll
            for (int nt = 0; nt < 4; nt++) {
                int n = wn * 32 + nt * 8 + gr;
                bf[nt][0] = __float_as_uint(Bs[buf][n][k8 * 8 + q]);
                bf[nt][1] = __float_as_uint(Bs[buf][n][k8 * 8 + q + 4]);
            }
            #pragma unroll
            for (int mt = 0; mt < 4; mt++)
                #pragma unroll
                for (int nt = 0; nt < 4; nt++)
                    mma_tf32(acc[mt][nt], af[mt], bf[nt]);
        }
        // single sync per stage: next iteration writes the other buffer, and the
        // rendezvous above already orders prior-stage reads before those writes.
    }
    __syncthreads();

    if (tid < BN) colacc[tid] = 0.0f;
    __syncthreads();

    float nc0v[4], nc1v[4];
    #pragma unroll
    for (int nt = 0; nt < 4; nt++) {
        int c = bn * BN + wn * 32 + nt * 8 + 2 * q;
        nc0v[nt] = g_nc[c];
        nc1v[nt] = g_nc[c + 1];
    }

    float es0[4], es1[4];
    #pragma unroll
    for (int nt = 0; nt < 4; nt++) { es0[nt] = 0.f; es1[nt] = 0.f; }

    #pragma unroll
    for (int mt = 0; mt < 4; mt++) {
        int r = bm * BM + wm * 64 + mt * 16 + gr;
        float na0 = na[r], na1 = na[r + 8];
        #pragma unroll
        for (int nt = 0; nt < 4; nt++) {
            int c = bn * BN + wn * 32 + nt * 8 + 2 * q;
            float t00 = distf(na0 + nc0v[nt] - 2.0f * acc[mt][nt][0]);
            float t01 = distf(na0 + nc1v[nt] - 2.0f * acc[mt][nt][1]);
            float t10 = distf(na1 + nc0v[nt] - 2.0f * acc[mt][nt][2]);
            float t11 = distf(na1 + nc1v[nt] - 2.0f * acc[mt][nt][3]);
            *(float2*)&T[(size_t)r * KC + c]       = make_float2(t00, t01);
            *(float2*)&T[(size_t)(r + 8) * KC + c] = make_float2(t10, t11);
            es0[nt] += __expf(t00) + __expf(t10);
            es1[nt] += __expf(t01) + __expf(t11);
        }
    }

    #pragma unroll
    for (int nt = 0; nt < 4; nt++) {
        int cl = wn * 32 + nt * 8 + 2 * q;
        atomicAdd(&colacc[cl], es0[nt]);
        atomicAdd(&colacc[cl + 1], es1[nt]);
    }
    __syncthreads();

    int csbase = (which * 2 + (bm >> 7)) * KC;
    if (tid < BN)
        atomicAdd(&g_cs[csbase + bn * BN + tid], colacc[tid]);
}

__global__ void logcs_kernel() {
    int i = blockIdx.x * blockDim.x + threadIdx.x;
    if (i < 4 * KC) g_lcs[i] = logf(g_cs[i]);
}

__device__ __forceinline__ float block_reduce(float v, float* red) {
    int t = threadIdx.x;
    red[t] = v;
    __syncthreads();
    for (int s = 128; s > 0; s >>= 1) {
        if (t < s) red[t] += red[t + s];
        __syncthreads();
    }
    float r = red[0];
    __syncthreads();
    return r;
}

__global__ __launch_bounds__(256) void final_kernel() {
    __shared__ float red[256];
    int b = blockIdx.x;
    int t = threadIdx.x;

    float az1[4], az2[4], lp[4];
    float az1s = 0.f, az2s = 0.f, ap1s = 0.f, ap2s = 0.f;
    #pragma unroll
    for (int j = 0; j < 4; j++) {
        int k = t + j * 256;
        float tz1 = g_tz[(size_t)b * KC + k];
        float tz2 = g_tz[(size_t)(b + B_HALF) * KC + k];
        float tp1 = g_tp[(size_t)b * KC + k];
        float tp2 = g_tp[(size_t)(b + B_HALF) * KC + k];
        float u1 = tz1 - g_lcs[k];
        float u2 = tz2 - g_lcs[KC + k];
        float v1 = tp1 - g_lcs[2 * KC + k];
        float v2 = tp2 - g_lcs[3 * KC + k];
        az1[j] = __expf(u1); az1s += az1[j];
        az2[j] = __expf(u2); az2s += az2[j];
        ap1s += __expf(v1);
        ap2s += __expf(v2);
        lp[j] = v1 + v2;
    }
    float rz1 = block_reduce(az1s, red);
    float rz2 = block_reduce(az2s, red);
    float rp1 = block_reduce(ap1s, red);
    float rp2 = block_reduce(ap2s, red);
    float lr = logf(rp1) + logf(rp2);
    float irz1 = 1.0f / rz1;
    float irz2 = 1.0f / rz2;
    float dot = 0.f;
    #pragma unroll
    for (int j = 0; j < 4; j++)
        dot += (az1[j] * irz1 + az2[j] * irz2) * (lp[j] - lr);
    float dt = block_reduce(dot, red);
    if (t == 0)
        atomicAdd(&g_loss, -(double)dt / (4.0 * (double)B_HALF));
}

__global__ void finalize_kernel(float* out) {
    out[0] = (float)g_loss;
}

// ---------------- launch ----------------
extern "C" void kernel_launch(void* const* d_in, const int* in_sizes, int n_in,
                              void* d_out, int out_size) {
    const float* z = (const float*)d_in[0];
    const float* p = (const float*)d_in[1];
    const float* c = (const float*)d_in[2];
    float* out = (float*)d_out;

    zero_kernel<<<16, 256>>>();
    normalize_kernel<<<2 * TWO_B + KC, 256>>>(z, p, c);
    dim3 ggrid(KC / BN, TWO_B / BM, 2);
    gemm_dist_tc<<<ggrid, 256>>>();
    logcs_kernel<<<16, 256>>>();
    final_kernel<<<B_HALF, 256>>>();
    finalize_kernel<<<1, 1>>>(out);
}

// round 4
// speedup vs baseline: 2.8289x; 2.3215x over previous
#include <cuda_runtime.h>
#include <cuda_fp16.h>
#include <math.h>
#include <stdint.h>

#define TWO_B 32768
#define B_HALF 16384
#define DIM 256
#define KC 1024
#define BM 128
#define BN 128

// ---------------- device scratch (static, no allocation) ----------------
__device__ __align__(16) __half g_zh[(size_t)TWO_B * DIM];
__device__ __align__(16) __half g_ph[(size_t)TWO_B * DIM];
__device__ __align__(16) __half g_ch[(size_t)KC * DIM];
__device__ float g_nz[TWO_B];
__device__ float g_np[TWO_B];
__device__ float g_nc[KC];
__device__ float g_tz[(size_t)TWO_B * KC];
__device__ float g_tp[(size_t)TWO_B * KC];
__device__ float g_cs[4 * KC];
__device__ float g_lcs[4 * KC];
__device__ double g_loss;

// ---------------- PTX helpers ----------------
__device__ __forceinline__ uint32_t smem_u32(const void* p) {
    uint32_t a;
    asm("{ .reg .u64 t; cvta.to.shared.u64 t, %1; cvt.u32.u64 %0, t; }" : "=r"(a) : "l"(p));
    return a;
}
#define CP_ASYNC16(dst, src) \
    asm volatile("cp.async.cg.shared.global [%0], [%1], 16;" :: "r"(dst), "l"(src) : "memory")
#define CP_COMMIT() asm volatile("cp.async.commit_group;" ::: "memory")
#define CP_WAIT(n)  asm volatile("cp.async.wait_group %0;" :: "n"(n) : "memory")
#define LDSM_X4(r0, r1, r2, r3, addr) \
    asm volatile("ldmatrix.sync.aligned.m8n8.x4.shared.b16 {%0,%1,%2,%3}, [%4];" \
                 : "=r"(r0), "=r"(r1), "=r"(r2), "=r"(r3) : "r"(addr))

__device__ __forceinline__ void mma_f16(float* c, const uint32_t* a, const uint32_t* b) {
    asm volatile(
        "mma.sync.aligned.m16n8k16.row.col.f32.f16.f16.f32 "
        "{%0,%1,%2,%3}, {%4,%5,%6,%7}, {%8,%9}, {%0,%1,%2,%3};"
        : "+f"(c[0]), "+f"(c[1]), "+f"(c[2]), "+f"(c[3])
        : "r"(a[0]), "r"(a[1]), "r"(a[2]), "r"(a[3]), "r"(b[0]), "r"(b[1]));
}

__device__ __forceinline__ float distf(float sq) {
    return 20.0f * sqrtf(fmaxf(sq, 1e-12f));
}

// ---------------- small kernels ----------------
__global__ void zero_kernel() {
    int i = blockIdx.x * blockDim.x + threadIdx.x;
    if (i < 4 * KC) g_cs[i] = 0.0f;
    if (i == 0) g_loss = 0.0;
}

// one warp per row; 8 rows/block
__global__ __launch_bounds__(256) void normalize_kernel(const float* __restrict__ z,
                                                        const float* __restrict__ p,
                                                        const float* __restrict__ c) {
    int row = blockIdx.x * 8 + (threadIdx.x >> 5);
    int lane = threadIdx.x & 31;
    const float* src; __half* dst; float* nsq; int r;
    if (row < TWO_B)          { src = z; dst = g_zh; nsq = g_nz; r = row; }
    else if (row < 2 * TWO_B) { src = p; dst = g_ph; nsq = g_np; r = row - TWO_B; }
    else                      { src = c; dst = g_ch; nsq = g_nc; r = row - 2 * TWO_B; }

    const float4* s4 = reinterpret_cast<const float4*>(src + (size_t)r * DIM);
    float4 v0 = s4[lane * 2];
    float4 v1 = s4[lane * 2 + 1];
    float ss = v0.x * v0.x + v0.y * v0.y + v0.z * v0.z + v0.w * v0.w
             + v1.x * v1.x + v1.y * v1.y + v1.z * v1.z + v1.w * v1.w;
    #pragma unroll
    for (int o = 16; o > 0; o >>= 1)
        ss += __shfl_xor_sync(0xffffffffu, ss, o);
    float inv = 1.0f / fmaxf(sqrtf(ss), 1e-12f);

    __half2 h[4];
    h[0] = __floats2half2_rn(v0.x * inv, v0.y * inv);
    h[1] = __floats2half2_rn(v0.z * inv, v0.w * inv);
    h[2] = __floats2half2_rn(v1.x * inv, v1.y * inv);
    h[3] = __floats2half2_rn(v1.z * inv, v1.w * inv);
    *reinterpret_cast<uint4*>(dst + (size_t)r * DIM + lane * 8) = *reinterpret_cast<uint4*>(h);
    if (lane == 0) nsq[r] = ss * inv * inv;
}

// ---------------- fp16 HMMA GEMM + fused distance/exp epilogue ----------------
// grid = (KC/BN, TWO_B/BM, 2), block = 256
#define LDW 40            // padded halves per row (32 + 8)
#define TILE_STRIDE 10240 // 128 * 80 bytes per buffer

__global__ __launch_bounds__(256, 2) void gemm_dist_hmma() {
    __shared__ __align__(16) __half As[2][BM][LDW];
    __shared__ __align__(16) __half Bs[2][BN][LDW];
    __shared__ float colacc[BN];

    int tid = threadIdx.x;
    int lane = tid & 31;
    int wid = tid >> 5;
    int wm = wid >> 2;   // 0..1
    int wn = wid & 3;    // 0..3
    int q = lane & 3;
    int gr = lane >> 2;

    int which = blockIdx.z;
    int bm = blockIdx.y;
    int bn = blockIdx.x;

    const __half* Ag = (which ? g_ph : g_zh) + (size_t)(bm * BM) * DIM;
    const __half* Bg = g_ch + (size_t)(bn * BN) * DIM;
    const float* na = which ? g_np : g_nz;
    float* T = which ? g_tp : g_tz;

    uint32_t sA = smem_u32(&As[0][0][0]);
    uint32_t sB = smem_u32(&Bs[0][0][0]);

    int ltile = tid >> 7;       // 0 = A, 1 = B
    int lrow = tid & 127;
    const __half* gsrc = (ltile ? Bg : Ag) + (size_t)lrow * DIM;
    uint32_t sdst0 = (ltile ? sB : sA) + lrow * 80;

    float acc[4][4][4];
    #pragma unroll
    for (int i = 0; i < 4; i++)
        #pragma unroll
        for (int j = 0; j < 4; j++)
            #pragma unroll
            for (int k = 0; k < 4; k++)
                acc[i][j][k] = 0.0f;

    // prologue: load stage 0 into buf 0
    #pragma unroll
    for (int c2 = 0; c2 < 4; c2++)
        CP_ASYNC16(sdst0 + c2 * 16, gsrc + c2 * 8);
    CP_COMMIT();

    #pragma unroll
    for (int s = 0; s < 8; s++) {
        int buf = s & 1;
        if (s < 7) {
            const __half* g = gsrc + (s + 1) * 32;
            uint32_t d = sdst0 + ((s + 1) & 1) * TILE_STRIDE;
            #pragma unroll
            for (int c2 = 0; c2 < 4; c2++)
                CP_ASYNC16(d + c2 * 16, g + c2 * 8);
            CP_COMMIT();
            CP_WAIT(1);
        } else {
            CP_WAIT(0);
        }
        __syncthreads();

        uint32_t aB = sA + buf * TILE_STRIDE + (wm * 64 + (lane & 15)) * 80 + (lane >> 4) * 16;
        uint32_t bB = sB + buf * TILE_STRIDE + (wn * 32 + (lane & 7) + (lane >> 4) * 8) * 80
                      + ((lane >> 3) & 1) * 16;
        #pragma unroll
        for (int k16 = 0; k16 < 2; k16++) {
            uint32_t a[4][4], b[2][4];
            #pragma unroll
            for (int mt = 0; mt < 4; mt++)
                LDSM_X4(a[mt][0], a[mt][1], a[mt][2], a[mt][3],
                        aB + mt * (16 * 80) + k16 * 32);
            #pragma unroll
            for (int j = 0; j < 2; j++)
                LDSM_X4(b[j][0], b[j][1], b[j][2], b[j][3],
                        bB + j * (16 * 80) + k16 * 32);
            #pragma unroll
            for (int mt = 0; mt < 4; mt++)
                #pragma unroll
                for (int nt = 0; nt < 4; nt++)
                    mma_f16(acc[mt][nt], a[mt], &b[nt >> 1][(nt & 1) * 2]);
        }
        __syncthreads();
    }

    // ---------------- epilogue (validated in R2) ----------------
    if (tid < BN) colacc[tid] = 0.0f;
    __syncthreads();

    float nc0v[4], nc1v[4];
    #pragma unroll
    for (int nt = 0; nt < 4; nt++) {
        int c = bn * BN + wn * 32 + nt * 8 + 2 * q;
        nc0v[nt] = g_nc[c];
        nc1v[nt] = g_nc[c + 1];
    }

    float es0[4], es1[4];
    #pragma unroll
    for (int nt = 0; nt < 4; nt++) { es0[nt] = 0.f; es1[nt] = 0.f; }

    #pragma unroll
    for (int mt = 0; mt < 4; mt++) {
        int r = bm * BM + wm * 64 + mt * 16 + gr;
        float na0 = na[r], na1 = na[r + 8];
        #pragma unroll
        for (int nt = 0; nt < 4; nt++) {
            int c = bn * BN + wn * 32 + nt * 8 + 2 * q;
            float t00 = distf(na0 + nc0v[nt] - 2.0f * acc[mt][nt][0]);
            float t01 = distf(na0 + nc1v[nt] - 2.0f * acc[mt][nt][1]);
            float t10 = distf(na1 + nc0v[nt] - 2.0f * acc[mt][nt][2]);
            float t11 = distf(na1 + nc1v[nt] - 2.0f * acc[mt][nt][3]);
            *(float2*)&T[(size_t)r * KC + c]       = make_float2(t00, t01);
            *(float2*)&T[(size_t)(r + 8) * KC + c] = make_float2(t10, t11);
            es0[nt] += __expf(t00) + __expf(t10);
            es1[nt] += __expf(t01) + __expf(t11);
        }
    }

    #pragma unroll
    for (int nt = 0; nt < 4; nt++) {
        int cl = wn * 32 + nt * 8 + 2 * q;
        atomicAdd(&colacc[cl], es0[nt]);
        atomicAdd(&colacc[cl + 1], es1[nt]);
    }
    __syncthreads();

    int csbase = (which * 2 + (bm >> 7)) * KC;
    if (tid < BN)
        atomicAdd(&g_cs[csbase + bn * BN + tid], colacc[tid]);
}

// ---------------- tail kernels ----------------
__global__ void logcs_kernel() {
    int i = blockIdx.x * blockDim.x + threadIdx.x;
    if (i < 4 * KC) g_lcs[i] = logf(g_cs[i]);
}

__global__ __launch_bounds__(256) void final_kernel() {
    __shared__ float sm[32];
    int b = blockIdx.x;
    int t = threadIdx.x;
    int lane = t & 31;
    int wid = t >> 5;

    float az1[4], az2[4], lp[4];
    float az1s = 0.f, az2s = 0.f, ap1s = 0.f, ap2s = 0.f;
    #pragma unroll
    for (int j = 0; j < 4; j++) {
        int k = t + j * 256;
        float tz1 = g_tz[(size_t)b * KC + k];
        float tz2 = g_tz[(size_t)(b + B_HALF) * KC + k];
        float tp1 = g_tp[(size_t)b * KC + k];
        float tp2 = g_tp[(size_t)(b + B_HALF) * KC + k];
        float u1 = tz1 - g_lcs[k];
        float u2 = tz2 - g_lcs[KC + k];
        float v1 = tp1 - g_lcs[2 * KC + k];
        float v2 = tp2 - g_lcs[3 * KC + k];
        az1[j] = __expf(u1); az1s += az1[j];
        az2[j] = __expf(u2); az2s += az2[j];
        ap1s += __expf(v1);
        ap2s += __expf(v2);
        lp[j] = v1 + v2;
    }

    // block-reduce 4 sums via shuffles
    #pragma unroll
    for (int o = 16; o > 0; o >>= 1) {
        az1s += __shfl_xor_sync(0xffffffffu, az1s, o);
        az2s += __shfl_xor_sync(0xffffffffu, az2s, o);
        ap1s += __shfl_xor_sync(0xffffffffu, ap1s, o);
        ap2s += __shfl_xor_sync(0xffffffffu, ap2s, o);
    }
    if (lane == 0) {
        sm[wid * 4 + 0] = az1s; sm[wid * 4 + 1] = az2s;
        sm[wid * 4 + 2] = ap1s; sm[wid * 4 + 3] = ap2s;
    }
    __syncthreads();
    if (t < 32) {
        float v = sm[t];
        v += __shfl_xor_sync(0xffffffffu, v, 4);
        v += __shfl_xor_sync(0xffffffffu, v, 8);
        v += __shfl_xor_sync(0xffffffffu, v, 16);
        if (t < 4) sm[t] = v;
    }
    __syncthreads();
    float rz1 = sm[0], rz2 = sm[1], rp1 = sm[2], rp2 = sm[3];

    float lr = logf(rp1) + logf(rp2);
    float irz1 = 1.0f / rz1;
    float irz2 = 1.0f / rz2;
    float dot = 0.f;
    #pragma unroll
    for (int j = 0; j < 4; j++)
        dot += (az1[j] * irz1 + az2[j] * irz2) * (lp[j] - lr);

    #pragma unroll
    for (int o = 16; o > 0; o >>= 1)
        dot += __shfl_xor_sync(0xffffffffu, dot, o);
    if (lane == 0) sm[8 + wid] = dot;
    __syncthreads();
    if (t < 32) {
        float v = (t < 8) ? sm[8 + t] : 0.f;
        v += __shfl_xor_sync(0xffffffffu, v, 1);
        v += __shfl_xor_sync(0xffffffffu, v, 2);
        v += __shfl_xor_sync(0xffffffffu, v, 4);
        if (t == 0)
            atomicAdd(&g_loss, -(double)v / (4.0 * (double)B_HALF));
    }
}

__global__ void finalize_kernel(float* out) {
    out[0] = (float)g_loss;
}

// ---------------- launch ----------------
extern "C" void kernel_launch(void* const* d_in, const int* in_sizes, int n_in,
                              void* d_out, int out_size) {
    const float* z = (const float*)d_in[0];
    const float* p = (const float*)d_in[1];
    const float* c = (const float*)d_in[2];
    float* out = (float*)d_out;

    zero_kernel<<<16, 256>>>();
    normalize_kernel<<<(2 * TWO_B + KC) / 8, 256>>>(z, p, c);
    dim3 ggrid(KC / BN, TWO_B / BM, 2);
    gemm_dist_hmma<<<ggrid, 256>>>();
    logcs_kernel<<<16, 256>>>();
    final_kernel<<<B_HALF, 256>>>();
    finalize_kernel<<<1, 1>>>(out);
}

// round 5
// speedup vs baseline: 2.8846x; 1.0197x over previous
#include <cuda_runtime.h>
#include <cuda_fp16.h>
#include <math.h>
#include <stdint.h>

#define TWO_B 32768
#define B_HALF 16384
#define DIM 256
#define KC 1024
#define BM 128
#define BN 128

// ---------------- device scratch (static, no allocation) ----------------
__device__ __align__(16) __half g_zh[(size_t)TWO_B * DIM];
__device__ __align__(16) __half g_ph[(size_t)TWO_B * DIM];
__device__ __align__(16) __half g_ch[(size_t)KC * DIM];
__device__ float g_nz[TWO_B];
__device__ float g_np[TWO_B];
__device__ float g_nc[KC];
__device__ __align__(16) __half g_tz[(size_t)TWO_B * KC];   // t stored fp16 (64 MB)
__device__ __align__(16) __half g_tp[(size_t)TWO_B * KC];
__device__ float g_cs[4 * KC];
__device__ float g_lcs[4 * KC];
__device__ double g_loss;

// ---------------- PTX helpers ----------------
__device__ __forceinline__ uint32_t smem_u32(const void* p) {
    uint32_t a;
    asm("{ .reg .u64 t; cvta.to.shared.u64 t, %1; cvt.u32.u64 %0, t; }" : "=r"(a) : "l"(p));
    return a;
}
#define CP_ASYNC16(dst, src) \
    asm volatile("cp.async.cg.shared.global [%0], [%1], 16;" :: "r"(dst), "l"(src) : "memory")
#define CP_COMMIT() asm volatile("cp.async.commit_group;" ::: "memory")
#define CP_WAIT(n)  asm volatile("cp.async.wait_group %0;" :: "n"(n) : "memory")
#define LDSM_X4(r0, r1, r2, r3, addr) \
    asm volatile("ldmatrix.sync.aligned.m8n8.x4.shared.b16 {%0,%1,%2,%3}, [%4];" \
                 : "=r"(r0), "=r"(r1), "=r"(r2), "=r"(r3) : "r"(addr))

__device__ __forceinline__ void mma_f16(float* c, const uint32_t* a, const uint32_t* b) {
    asm volatile(
        "mma.sync.aligned.m16n8k16.row.col.f32.f16.f16.f32 "
        "{%0,%1,%2,%3}, {%4,%5,%6,%7}, {%8,%9}, {%0,%1,%2,%3};"
        : "+f"(c[0]), "+f"(c[1]), "+f"(c[2]), "+f"(c[3])
        : "r"(a[0]), "r"(a[1]), "r"(a[2]), "r"(a[3]), "r"(b[0]), "r"(b[1]));
}

__device__ __forceinline__ float distf(float sq) {
    return 20.0f * sqrtf(fmaxf(sq, 1e-12f));
}

// ---------------- small kernels ----------------
__global__ void zero_kernel() {
    int i = blockIdx.x * blockDim.x + threadIdx.x;
    if (i < 4 * KC) g_cs[i] = 0.0f;
    if (i == 0) g_loss = 0.0;
}

// one warp per row; 8 rows/block
__global__ __launch_bounds__(256) void normalize_kernel(const float* __restrict__ z,
                                                        const float* __restrict__ p,
                                                        const float* __restrict__ c) {
    int row = blockIdx.x * 8 + (threadIdx.x >> 5);
    int lane = threadIdx.x & 31;
    const float* src; __half* dst; float* nsq; int r;
    if (row < TWO_B)          { src = z; dst = g_zh; nsq = g_nz; r = row; }
    else if (row < 2 * TWO_B) { src = p; dst = g_ph; nsq = g_np; r = row - TWO_B; }
    else                      { src = c; dst = g_ch; nsq = g_nc; r = row - 2 * TWO_B; }

    const float4* s4 = reinterpret_cast<const float4*>(src + (size_t)r * DIM);
    float4 v0 = s4[lane * 2];
    float4 v1 = s4[lane * 2 + 1];
    float ss = v0.x * v0.x + v0.y * v0.y + v0.z * v0.z + v0.w * v0.w
             + v1.x * v1.x + v1.y * v1.y + v1.z * v1.z + v1.w * v1.w;
    #pragma unroll
    for (int o = 16; o > 0; o >>= 1)
        ss += __shfl_xor_sync(0xffffffffu, ss, o);
    float inv = 1.0f / fmaxf(sqrtf(ss), 1e-12f);

    __half2 h[4];
    h[0] = __floats2half2_rn(v0.x * inv, v0.y * inv);
    h[1] = __floats2half2_rn(v0.z * inv, v0.w * inv);
    h[2] = __floats2half2_rn(v1.x * inv, v1.y * inv);
    h[3] = __floats2half2_rn(v1.z * inv, v1.w * inv);
    *reinterpret_cast<uint4*>(dst + (size_t)r * DIM + lane * 8) = *reinterpret_cast<uint4*>(h);
    if (lane == 0) nsq[r] = ss * inv * inv;
}

// ---------------- fp16 HMMA GEMM + fused distance/exp epilogue ----------------
// grid = (KC/BN, TWO_B/BM, 2), block = 256, dynamic smem
#define NS 4              // pipeline stages
#define NSTAGES_K 8       // 256 / 32
#define STAGE_B 10240     // 128 rows * 80 bytes
#define SMEM_TOTAL (2 * NS * STAGE_B + 512)

__global__ __launch_bounds__(256, 2) void gemm_dist_hmma() {
    extern __shared__ char dsm[];
    uint32_t sA = smem_u32(dsm);
    uint32_t sB = sA + NS * STAGE_B;
    float* colacc = reinterpret_cast<float*>(dsm + 2 * NS * STAGE_B);

    int tid = threadIdx.x;
    int lane = tid & 31;
    int wid = tid >> 5;
    int wm = wid >> 2;   // 0..1
    int wn = wid & 3;    // 0..3
    int q = lane & 3;
    int gr = lane >> 2;

    int which = blockIdx.z;
    int bm = blockIdx.y;
    int bn = blockIdx.x;

    const __half* Ag = (which ? g_ph : g_zh) + (size_t)(bm * BM) * DIM;
    const __half* Bg = g_ch + (size_t)(bn * BN) * DIM;
    const float* na = which ? g_np : g_nz;
    __half* T = which ? g_tp : g_tz;

    int ltile = tid >> 7;       // 0 = A, 1 = B
    int lrow = tid & 127;
    const __half* gsrc = (ltile ? Bg : Ag) + (size_t)lrow * DIM;
    uint32_t sdst = (ltile ? sB : sA) + lrow * 80;

    float acc[4][4][4];
    #pragma unroll
    for (int i = 0; i < 4; i++)
        #pragma unroll
        for (int j = 0; j < 4; j++)
            #pragma unroll
            for (int k = 0; k < 4; k++)
                acc[i][j][k] = 0.0f;

    // prologue: issue stages 0..NS-2
    #pragma unroll
    for (int ps = 0; ps < NS - 1; ps++) {
        uint32_t d = sdst + (ps & (NS - 1)) * STAGE_B;
        const __half* g = gsrc + ps * 32;
        #pragma unroll
        for (int c2 = 0; c2 < 4; c2++)
            CP_ASYNC16(d + c2 * 16, g + c2 * 8);
        CP_COMMIT();
    }

    #pragma unroll
    for (int s = 0; s < NSTAGES_K; s++) {
        CP_WAIT(NS - 2);        // stage s arrived
        __syncthreads();        // all warps done reading buf (s-1)&3

        if (s + NS - 1 < NSTAGES_K) {
            uint32_t d = sdst + ((s + NS - 1) & (NS - 1)) * STAGE_B;
            const __half* g = gsrc + (s + NS - 1) * 32;
            #pragma unroll
            for (int c2 = 0; c2 < 4; c2++)
                CP_ASYNC16(d + c2 * 16, g + c2 * 8);
        }
        CP_COMMIT();            // always commit (possibly empty group)

        int buf = s & (NS - 1);
        uint32_t aB = sA + buf * STAGE_B + (wm * 64 + (lane & 15)) * 80 + (lane >> 4) * 16;
        uint32_t bB = sB + buf * STAGE_B + (wn * 32 + (lane & 7) + (lane >> 4) * 8) * 80
                      + ((lane >> 3) & 1) * 16;
        #pragma unroll
        for (int k16 = 0; k16 < 2; k16++) {
            uint32_t a[4][4], b[2][4];
            #pragma unroll
            for (int mt = 0; mt < 4; mt++)
                LDSM_X4(a[mt][0], a[mt][1], a[mt][2], a[mt][3],
                        aB + mt * (16 * 80) + k16 * 32);
            #pragma unroll
            for (int j = 0; j < 2; j++)
                LDSM_X4(b[j][0], b[j][1], b[j][2], b[j][3],
                        bB + j * (16 * 80) + k16 * 32);
            #pragma unroll
            for (int mt = 0; mt < 4; mt++)
                #pragma unroll
                for (int nt = 0; nt < 4; nt++)
                    mma_f16(acc[mt][nt], a[mt], &b[nt >> 1][(nt & 1) * 2]);
        }
    }
    __syncthreads();

    // ---------------- epilogue ----------------
    if (tid < BN) colacc[tid] = 0.0f;
    __syncthreads();

    float nc0v[4], nc1v[4];
    #pragma unroll
    for (int nt = 0; nt < 4; nt++) {
        int c = bn * BN + wn * 32 + nt * 8 + 2 * q;
        nc0v[nt] = g_nc[c];
        nc1v[nt] = g_nc[c + 1];
    }

    float es0[4], es1[4];
    #pragma unroll
    for (int nt = 0; nt < 4; nt++) { es0[nt] = 0.f; es1[nt] = 0.f; }

    #pragma unroll
    for (int mt = 0; mt < 4; mt++) {
        int r = bm * BM + wm * 64 + mt * 16 + gr;
        float na0 = na[r], na1 = na[r + 8];
        #pragma unroll
        for (int nt = 0; nt < 4; nt++) {
            int c = bn * BN + wn * 32 + nt * 8 + 2 * q;
            float t00 = distf(na0 + nc0v[nt] - 2.0f * acc[mt][nt][0]);
            float t01 = distf(na0 + nc1v[nt] - 2.0f * acc[mt][nt][1]);
            float t10 = distf(na1 + nc0v[nt] - 2.0f * acc[mt][nt][2]);
            float t11 = distf(na1 + nc1v[nt] - 2.0f * acc[mt][nt][3]);
            *(__half2*)&T[(size_t)r * KC + c]       = __floats2half2_rn(t00, t01);
            *(__half2*)&T[(size_t)(r + 8) * KC + c] = __floats2half2_rn(t10, t11);
            es0[nt] += __expf(t00) + __expf(t10);
            es1[nt] += __expf(t01) + __expf(t11);
        }
    }

    #pragma unroll
    for (int nt = 0; nt < 4; nt++) {
        int cl = wn * 32 + nt * 8 + 2 * q;
        atomicAdd(&colacc[cl], es0[nt]);
        atomicAdd(&colacc[cl + 1], es1[nt]);
    }
    __syncthreads();

    int csbase = (which * 2 + (bm >> 7)) * KC;
    if (tid < BN)
        atomicAdd(&g_cs[csbase + bn * BN + tid], colacc[tid]);
}

// ---------------- tail kernels ----------------
__global__ void logcs_kernel() {
    int i = blockIdx.x * blockDim.x + threadIdx.x;
    if (i < 4 * KC) g_lcs[i] = logf(g_cs[i]);
}

__global__ __launch_bounds__(256) void final_kernel() {
    __shared__ float sm[32];
    int b = blockIdx.x;
    int t = threadIdx.x;
    int lane = t & 31;
    int wid = t >> 5;
    int k0 = t * 4;

    // coalesced 8B loads: 4 consecutive k per thread, per matrix
    uint2 rz1 = *(const uint2*)(g_tz + (size_t)b * KC + k0);
    uint2 rz2 = *(const uint2*)(g_tz + (size_t)(b + B_HALF) * KC + k0);
    uint2 rp1 = *(const uint2*)(g_tp + (size_t)b * KC + k0);
    uint2 rp2 = *(const uint2*)(g_tp + (size_t)(b + B_HALF) * KC + k0);
    float4 l1 = *(const float4*)(g_lcs + k0);
    float4 l2 = *(const float4*)(g_lcs + KC + k0);
    float4 l3 = *(const float4*)(g_lcs + 2 * KC + k0);
    float4 l4 = *(const float4*)(g_lcs + 3 * KC + k0);

    float tz1[4], tz2[4], tp1[4], tp2[4];
    {
        float2 a, bb;
        a = __half22float2(*(__half2*)&rz1.x); bb = __half22float2(*(__half2*)&rz1.y);
        tz1[0] = a.x; tz1[1] = a.y; tz1[2] = bb.x; tz1[3] = bb.y;
        a = __half22float2(*(__half2*)&rz2.x); bb = __half22float2(*(__half2*)&rz2.y);
        tz2[0] = a.x; tz2[1] = a.y; tz2[2] = bb.x; tz2[3] = bb.y;
        a = __half22float2(*(__half2*)&rp1.x); bb = __half22float2(*(__half2*)&rp1.y);
        tp1[0] = a.x; tp1[1] = a.y; tp1[2] = bb.x; tp1[3] = bb.y;
        a = __half22float2(*(__half2*)&rp2.x); bb = __half22float2(*(__half2*)&rp2.y);
        tp2[0] = a.x; tp2[1] = a.y; tp2[2] = bb.x; tp2[3] = bb.y;
    }
    float lc1[4] = {l1.x, l1.y, l1.z, l1.w};
    float lc2[4] = {l2.x, l2.y, l2.z, l2.w};
    float lc3[4] = {l3.x, l3.y, l3.z, l3.w};
    float lc4[4] = {l4.x, l4.y, l4.z, l4.w};

    float az1[4], az2[4], lp[4];
    float az1s = 0.f, az2s = 0.f, ap1s = 0.f, ap2s = 0.f;
    #pragma unroll
    for (int j = 0; j < 4; j++) {
        float u1 = tz1[j] - lc1[j];
        float u2 = tz2[j] - lc2[j];
        float v1 = tp1[j] - lc3[j];
        float v2 = tp2[j] - lc4[j];
        az1[j] = __expf(u1); az1s += az1[j];
        az2[j] = __expf(u2); az2s += az2[j];
        ap1s += __expf(v1);
        ap2s += __expf(v2);
        lp[j] = v1 + v2;
    }

    #pragma unroll
    for (int o = 16; o > 0; o >>= 1) {
        az1s += __shfl_xor_sync(0xffffffffu, az1s, o);
        az2s += __shfl_xor_sync(0xffffffffu, az2s, o);
        ap1s += __shfl_xor_sync(0xffffffffu, ap1s, o);
        ap2s += __shfl_xor_sync(0xffffffffu, ap2s, o);
    }
    if (lane == 0) {
        sm[wid * 4 + 0] = az1s; sm[wid * 4 + 1] = az2s;
        sm[wid * 4 + 2] = ap1s; sm[wid * 4 + 3] = ap2s;
    }
    __syncthreads();
    if (t < 32) {
        float v = sm[t];
        v += __shfl_xor_sync(0xffffffffu, v, 4);
        v += __shfl_xor_sync(0xffffffffu, v, 8);
        v += __shfl_xor_sync(0xffffffffu, v, 16);
        if (t < 4) sm[t] = v;
    }
    __syncthreads();
    float rz1s = sm[0], rz2s = sm[1], rp1s = sm[2], rp2s = sm[3];

    float lr = logf(rp1s) + logf(rp2s);
    float irz1 = 1.0f / rz1s;
    float irz2 = 1.0f / rz2s;
    float dot = 0.f;
    #pragma unroll
    for (int j = 0; j < 4; j++)
        dot += (az1[j] * irz1 + az2[j] * irz2) * (lp[j] - lr);

    #pragma unroll
    for (int o = 16; o > 0; o >>= 1)
        dot += __shfl_xor_sync(0xffffffffu, dot, o);
    if (lane == 0) sm[8 + wid] = dot;
    __syncthreads();
    if (t < 32) {
        float v = (t < 8) ? sm[8 + t] : 0.f;
        v += __shfl_xor_sync(0xffffffffu, v, 1);
        v += __shfl_xor_sync(0xffffffffu, v, 2);
        v += __shfl_xor_sync(0xffffffffu, v, 4);
        if (t == 0)
            atomicAdd(&g_loss, -(double)v / (4.0 * (double)B_HALF));
    }
}

__global__ void finalize_kernel(float* out) {
    out[0] = (float)g_loss;
}

// ---------------- launch ----------------
extern "C" void kernel_launch(void* const* d_in, const int* in_sizes, int n_in,
                              void* d_out, int out_size) {
    const float* z = (const float*)d_in[0];
    const float* p = (const float*)d_in[1];
    const float* c = (const float*)d_in[2];
    float* out = (float*)d_out;

    cudaFuncSetAttribute(gemm_dist_hmma, cudaFuncAttributeMaxDynamicSharedMemorySize, SMEM_TOTAL);

    zero_kernel<<<16, 256>>>();
    normalize_kernel<<<(2 * TWO_B + KC) / 8, 256>>>(z, p, c);
    dim3 ggrid(KC / BN, TWO_B / BM, 2);
    gemm_dist_hmma<<<ggrid, 256, SMEM_TOTAL>>>();
    logcs_kernel<<<16, 256>>>();
    final_kernel<<<B_HALF, 256>>>();
    finalize_kernel<<<1, 1>>>(out);
}